// round 10
// baseline (speedup 1.0000x reference)
#include <cuda_runtime.h>
#include <cuda_bf16.h>

// WaveletTransform: 3-level low-pass pyramid on x[8,32,512,512] fp32.
// out = x, except per-channel:
//   out[0:256,0:256] = down2x(conv3x3(x[0:512,0:512]))        (level 0)
//   out[0:128,0:128] = down2x(conv3x3(level0 result[0:256]^2)) (level 1)
//   out[0: 64,0: 64] = down2x(conv3x3(level1 result[0:128]^2)) (level 2)
// conv = outer([.25,.5,.25],[.25,.5,.25]), zero-padded 'same', even-index
// downsample (center 2i,2j -> taps 2i-1..2i+1).
//
// R10: K1 = exact R3 shape (best measured: 78.6us). Copy-path LOADS now
//      __ldcs (stores were already .cs): the 384MB pure stream is tagged
//      evict-first in L2 so the 64MB level-0 conv output (normal stores)
//      survives in L2 for K23's re-read. K23 = exact R4 version.
//      (R8 race rejected; R9 MLP-8 K1 regressed and is reverted.)

#define BC_TOTAL (8 * 32)
#define H0 512
#define W0C 512

#define L1_STRIDE 132                       // 128 + 4 floats pad
#define K23_SMEM (128 * L1_STRIDE * 4)      // 67584 bytes

__device__ __forceinline__ float hfilt(float a, float b, float c) {
    return 0.25f * a + 0.5f * b + 0.25f * c;
}

// ---------------------------------------------------------------------------
// K1: fused identity copy + level-0 conv-down into top-left 256^2.
// grid (1,64,256), block 256. sub = tid>>7 selects a 4-row group; each thread
// owns column group j4 (float4) across 4 consecutive rows.
// Copy path: __ldcs loads + __stcs stores (pure stream, evict-first).
// ---------------------------------------------------------------------------
__global__ void __launch_bounds__(256) k1_copy_down0(
    const float* __restrict__ x, float* __restrict__ out)
{
    const int j4   = threadIdx.x & 127;          // 0..127 (col/4)
    const int sub  = threadIdx.x >> 7;           // 0..1
    const int base = blockIdx.y * 8 + sub * 4;   // first of 4 rows
    const int bc   = blockIdx.z;

    const float* xp = x   + (size_t)bc * H0 * W0C;
    float*       op = out + (size_t)bc * H0 * W0C;

    if (base < 256 && j4 < 64) {
        #pragma unroll
        for (int it = 0; it < 4; it++) {
            const int i  = base + it;
            const int r0 = 2 * i - 1;            // -1 only when i==0
            float acc0 = 0.f, acc1 = 0.f, acc2 = 0.f, acc3 = 0.f;
            #pragma unroll
            for (int a = 0; a < 3; a++) {
                const int r = r0 + a;            // <= 511
                if (r < 0) continue;             // warp-uniform
                const float wr = (a == 1) ? 0.5f : 0.25f;
                const float* row = xp + (size_t)r * W0C;
                const float4* rv = reinterpret_cast<const float4*>(row) + 2 * j4;
                float4 p0 = rv[0];
                float4 p1 = rv[1];
                float left = __shfl_up_sync(0xFFFFFFFFu, p1.w, 1);
                if ((j4 & 31) == 0)
                    left = (j4 == 0) ? 0.f : row[8 * j4 - 1];
                acc0 += wr * hfilt(left, p0.x, p0.y);
                acc1 += wr * hfilt(p0.y, p0.z, p0.w);
                acc2 += wr * hfilt(p0.w, p1.x, p1.y);
                acc3 += wr * hfilt(p1.y, p1.z, p1.w);
            }
            *reinterpret_cast<float4*>(op + (size_t)i * W0C + 4 * j4) =
                make_float4(acc0, acc1, acc2, acc3);
        }
    } else {
        float4 v[4];
        #pragma unroll
        for (int it = 0; it < 4; it++)
            v[it] = __ldcs(reinterpret_cast<const float4*>(
                               xp + (size_t)(base + it) * W0C) + j4);
        #pragma unroll
        for (int it = 0; it < 4; it++)
            __stcs(reinterpret_cast<float4*>(
                       op + (size_t)(base + it) * W0C) + j4, v[it]);
    }
}

// ---------------------------------------------------------------------------
// K23: fused levels 1+2 (exact R4 version). One CTA per channel, 1024
// threads, level-1 in smem.
// Phase 1: level-1 conv from out[0:256]^2 (stride 512) -> smem [128][132].
// Phase 2: out[0:128]^2 <- inner 64^2 conv of smem, remainder smem copy.
// ---------------------------------------------------------------------------
__global__ void __launch_bounds__(1024) k23_fused(float* __restrict__ out)
{
    extern __shared__ float l1[];               // [128][L1_STRIDE]
    const int lane = threadIdx.x & 31;
    const int wy   = threadIdx.x >> 5;          // 0..31
    const int bc   = blockIdx.x;

    float* op = out + (size_t)bc * H0 * W0C;

    // Phase 1: level-1 conv (reads level-0 result written by K1)
    #pragma unroll
    for (int it = 0; it < 4; it++) {
        const int i  = wy * 4 + it;             // 0..127
        const int r0 = 2 * i - 1;
        float acc0 = 0.f, acc1 = 0.f, acc2 = 0.f, acc3 = 0.f;
        #pragma unroll
        for (int a = 0; a < 3; a++) {
            const int r = r0 + a;               // <= 255
            if (r < 0) continue;                // warp-uniform
            const float wr = (a == 1) ? 0.5f : 0.25f;
            const float* row = op + (size_t)r * W0C;
            const float4* rv = reinterpret_cast<const float4*>(row) + 2 * lane;
            float4 p0 = rv[0];
            float4 p1 = rv[1];
            float left = __shfl_up_sync(0xFFFFFFFFu, p1.w, 1);
            if (lane == 0) left = 0.f;
            acc0 += wr * hfilt(left, p0.x, p0.y);
            acc1 += wr * hfilt(p0.y, p0.z, p0.w);
            acc2 += wr * hfilt(p0.w, p1.x, p1.y);
            acc3 += wr * hfilt(p1.y, p1.z, p1.w);
        }
        *reinterpret_cast<float4*>(&l1[i * L1_STRIDE + 4 * lane]) =
            make_float4(acc0, acc1, acc2, acc3);
    }
    __syncthreads();

    // Phase 2: level-2 conv (inner 64^2) + copy, write out[0:128]^2
    #pragma unroll
    for (int it = 0; it < 4; it++) {
        const int i = wy * 4 + it;              // 0..127
        float4 val;
        if (i < 64 && lane < 16) {
            const int r0 = 2 * i - 1;
            float acc0 = 0.f, acc1 = 0.f, acc2 = 0.f, acc3 = 0.f;
            #pragma unroll
            for (int a = 0; a < 3; a++) {
                const int r = r0 + a;           // <= 127
                if (r < 0) continue;
                const float wr = (a == 1) ? 0.5f : 0.25f;
                const float* row = &l1[r * L1_STRIDE];
                float4 p0 = *reinterpret_cast<const float4*>(row + 8 * lane);
                float4 p1 = *reinterpret_cast<const float4*>(row + 8 * lane + 4);
                float left = __shfl_up_sync(0x0000FFFFu, p1.w, 1);
                if (lane == 0) left = 0.f;
                acc0 += wr * hfilt(left, p0.x, p0.y);
                acc1 += wr * hfilt(p0.y, p0.z, p0.w);
                acc2 += wr * hfilt(p0.w, p1.x, p1.y);
                acc3 += wr * hfilt(p1.y, p1.z, p1.w);
            }
            val = make_float4(acc0, acc1, acc2, acc3);
        } else {
            val = *reinterpret_cast<const float4*>(&l1[i * L1_STRIDE + 4 * lane]);
        }
        *reinterpret_cast<float4*>(op + (size_t)i * W0C + 4 * lane) = val;
    }
}

extern "C" void kernel_launch(void* const* d_in, const int* in_sizes, int n_in,
                              void* d_out, int out_size)
{
    (void)in_sizes; (void)n_in; (void)out_size;
    const float* x = (const float*)d_in[0];
    float* out = (float*)d_out;

    static bool attr_set = false;
    if (!attr_set) {
        cudaFuncSetAttribute(k23_fused,
                             cudaFuncAttributeMaxDynamicSharedMemorySize,
                             K23_SMEM);
        attr_set = true;
    }

    k1_copy_down0<<<dim3(1, 64, BC_TOTAL), dim3(256)>>>(x, out);
    k23_fused    <<<dim3(BC_TOTAL), dim3(1024), K23_SMEM>>>(out);
}

// round 11
// speedup vs baseline: 1.2120x; 1.2120x over previous
#include <cuda_runtime.h>
#include <cuda_bf16.h>

// WaveletTransform: 3-level low-pass pyramid on x[8,32,512,512] fp32.
// out = x, except per-channel:
//   out[0:256,0:256] = down2x(conv3x3(x[0:512,0:512]))        (level 0)
//   out[0:128,0:128] = down2x(conv3x3(level0 result[0:256]^2)) (level 1)
//   out[0: 64,0: 64] = down2x(conv3x3(level1 result[0:128]^2)) (level 2)
// conv = outer([.25,.5,.25],[.25,.5,.25]), zero-padded 'same', even-index
// downsample (center 2i,2j -> taps 2i-1..2i+1).
//
// R11: K1 = exact R3 shape (78.6us local optimum; R9/R10 variants regressed).
//      K23 decomposed: 4 strip-CTAs per channel (grid 1024, block 256,
//      17.4KB static smem) -> 8 CTAs/SM, ALL CTAs resident in one wave,
//      short per-CTA critical path. Each CTA: level-1 rows 32k-1..32k+31
//      into smem (halo row recomputed; zero row for k=0 top pad), then
//      level-2 rows 16k..16k+15 (1 float4/thread) + copy writes for rows
//      32k..32k+31 where (i>=64 or col>=64). Disjoint output ownership.

#define BC_TOTAL (8 * 32)
#define H0 512
#define W0C 512

#define L1S 132                          // 128 + 4 floats pad
#define L1_ROWS 33

__device__ __forceinline__ float hfilt(float a, float b, float c) {
    return 0.25f * a + 0.5f * b + 0.25f * c;
}

// ---------------------------------------------------------------------------
// K1: fused identity copy + level-0 conv-down into top-left 256^2.
// grid (1,64,256), block 256.  (exact R3/R4 version)
// ---------------------------------------------------------------------------
__global__ void __launch_bounds__(256) k1_copy_down0(
    const float* __restrict__ x, float* __restrict__ out)
{
    const int j4   = threadIdx.x & 127;          // 0..127 (col/4)
    const int sub  = threadIdx.x >> 7;           // 0..1
    const int base = blockIdx.y * 8 + sub * 4;   // first of 4 rows
    const int bc   = blockIdx.z;

    const float* xp = x   + (size_t)bc * H0 * W0C;
    float*       op = out + (size_t)bc * H0 * W0C;

    if (base < 256 && j4 < 64) {
        #pragma unroll
        for (int it = 0; it < 4; it++) {
            const int i  = base + it;
            const int r0 = 2 * i - 1;
            float acc0 = 0.f, acc1 = 0.f, acc2 = 0.f, acc3 = 0.f;
            #pragma unroll
            for (int a = 0; a < 3; a++) {
                const int r = r0 + a;            // <= 511
                if (r < 0) continue;             // warp-uniform
                const float wr = (a == 1) ? 0.5f : 0.25f;
                const float* row = xp + (size_t)r * W0C;
                const float4* rv = reinterpret_cast<const float4*>(row) + 2 * j4;
                float4 p0 = rv[0];
                float4 p1 = rv[1];
                float left = __shfl_up_sync(0xFFFFFFFFu, p1.w, 1);
                if ((j4 & 31) == 0)
                    left = (j4 == 0) ? 0.f : row[8 * j4 - 1];
                acc0 += wr * hfilt(left, p0.x, p0.y);
                acc1 += wr * hfilt(p0.y, p0.z, p0.w);
                acc2 += wr * hfilt(p0.w, p1.x, p1.y);
                acc3 += wr * hfilt(p1.y, p1.z, p1.w);
            }
            *reinterpret_cast<float4*>(op + (size_t)i * W0C + 4 * j4) =
                make_float4(acc0, acc1, acc2, acc3);
        }
    } else {
        float4 v[4];
        #pragma unroll
        for (int it = 0; it < 4; it++)
            v[it] = *(reinterpret_cast<const float4*>(
                          xp + (size_t)(base + it) * W0C) + j4);
        #pragma unroll
        for (int it = 0; it < 4; it++)
            __stcs(reinterpret_cast<float4*>(
                       op + (size_t)(base + it) * W0C) + j4, v[it]);
    }
}

// ---------------------------------------------------------------------------
// K23s: strip version of fused levels 1+2. grid (4, 256), block 256.
// CTA (k, bc): smem holds level-1 rows 32k-1 .. 32k+31 (33 rows, r1<0 = 0).
// ---------------------------------------------------------------------------
__global__ void __launch_bounds__(256) k23_strip(float* __restrict__ out)
{
    __shared__ float l1[L1_ROWS * L1S];

    const int tid  = threadIdx.x;
    const int lane = tid & 31;
    const int wid  = tid >> 5;                  // 0..7
    const int k    = blockIdx.x;                // strip 0..3
    const int bc   = blockIdx.y;

    float* op = out + (size_t)bc * H0 * W0C;

    // ---- Phase 1: level-1 conv -> smem rows 0..32 (r1 = 32k-1+r_local) ----
    #pragma unroll
    for (int t = 0; t < 5; t++) {
        const int r_local = 8 * t + wid;        // 0..39; valid <= 32
        if (r_local <= 32) {
            const int r1 = 32 * k - 1 + r_local;   // -1..127
            float acc0 = 0.f, acc1 = 0.f, acc2 = 0.f, acc3 = 0.f;
            if (r1 >= 0) {                      // warp-uniform
                const int r0v = 2 * r1 - 1;
                #pragma unroll
                for (int a = 0; a < 3; a++) {
                    const int r = r0v + a;      // <= 255
                    if (r < 0) continue;        // warp-uniform
                    const float wr = (a == 1) ? 0.5f : 0.25f;
                    const float* row = op + (size_t)r * W0C;
                    const float4* rv =
                        reinterpret_cast<const float4*>(row) + 2 * lane;
                    float4 p0 = rv[0];
                    float4 p1 = rv[1];
                    float left = __shfl_up_sync(0xFFFFFFFFu, p1.w, 1);
                    if (lane == 0) left = 0.f;
                    acc0 += wr * hfilt(left, p0.x, p0.y);
                    acc1 += wr * hfilt(p0.y, p0.z, p0.w);
                    acc2 += wr * hfilt(p0.w, p1.x, p1.y);
                    acc3 += wr * hfilt(p1.y, p1.z, p1.w);
                }
            }
            *reinterpret_cast<float4*>(&l1[r_local * L1S + 4 * lane]) =
                make_float4(acc0, acc1, acc2, acc3);   // zeros when r1 < 0
        }
    }
    __syncthreads();

    // ---- Phase 2a: level-2 rows 16k..16k+15, one float4 per thread ----
    {
        const int i2l = tid >> 4;               // 0..15
        const int g   = tid & 15;               // float4 col group
        float acc0 = 0.f, acc1 = 0.f, acc2 = 0.f, acc3 = 0.f;
        #pragma unroll
        for (int a = 0; a < 3; a++) {
            const int loc = 2 * i2l + a;        // 0..31 (row -1 = zero row)
            const float* row = &l1[loc * L1S];
            float4 p0 = *reinterpret_cast<const float4*>(row + 8 * g);
            float4 p1 = *reinterpret_cast<const float4*>(row + 8 * g + 4);
            const float wr = (a == 1) ? 0.5f : 0.25f;
            float left = __shfl_up_sync(0xFFFFFFFFu, p1.w, 1);
            if (g == 0) left = 0.f;
            acc0 += wr * hfilt(left, p0.x, p0.y);
            acc1 += wr * hfilt(p0.y, p0.z, p0.w);
            acc2 += wr * hfilt(p0.w, p1.x, p1.y);
            acc3 += wr * hfilt(p1.y, p1.z, p1.w);
        }
        *reinterpret_cast<float4*>(
            op + (size_t)(16 * k + i2l) * W0C + 4 * g) =
            make_float4(acc0, acc1, acc2, acc3);
    }

    // ---- Phase 2b: copy level-1 rows 32k..32k+31 where outside inner 64^2 ----
    #pragma unroll
    for (int q = 0; q < 4; q++) {
        const int idx = tid + 256 * q;          // 0..1023
        const int row = idx >> 5;               // 0..31
        const int j4  = idx & 31;               // 0..31
        const int i   = 32 * k + row;           // 0..127
        if (i >= 64 || j4 >= 16) {
            float4 v = *reinterpret_cast<const float4*>(
                           &l1[(row + 1) * L1S + 4 * j4]);
            *reinterpret_cast<float4*>(op + (size_t)i * W0C + 4 * j4) = v;
        }
    }
}

extern "C" void kernel_launch(void* const* d_in, const int* in_sizes, int n_in,
                              void* d_out, int out_size)
{
    (void)in_sizes; (void)n_in; (void)out_size;
    const float* x = (const float*)d_in[0];
    float* out = (float*)d_out;

    k1_copy_down0<<<dim3(1, 64, BC_TOTAL), dim3(256)>>>(x, out);
    k23_strip    <<<dim3(4, BC_TOTAL), dim3(256)>>>(out);
}